// round 4
// baseline (speedup 1.0000x reference)
#include <cuda_runtime.h>
#include <cuda_fp16.h>
#include <cstdint>

#define BV 8
#define TV 512
#define DV 2048
#define HV 2048
#define STEPS (BV * TV)
#define R4H (4 * HV)
#define GRID 148
#define JPC 14
#define ROWS (4 * JPC)
#define NTH 256
#define W_BYTES (ROWS * HV * 2)              /* 229376: tiled fp16 W slice */
#define LSTM_SMEM (W_BYTES + 2 * 64 * 4)     /* + pre_part[2][64] = 229888 */
#define OUTSTRIDE ((size_t)STEPS * HV)

__device__ float g_xp[(size_t)STEPS * R4H];
__device__ __align__(16) __half g_hh[2][HV];
__device__ unsigned int g_bar;

__device__ __forceinline__ uint32_t smem_u32(const void* p) {
    uint32_t a;
    asm("{ .reg .u64 t; cvta.to.shared.u64 t, %1; cvt.u32.u64 %0, t; }"
        : "=r"(a) : "l"(p));
    return a;
}

// ---------------------------------------------------------------- GEMM (+init)
#define GBK 16
#define GPAD 132
__global__ void __launch_bounds__(256, 2)
gemm_xp(const float* __restrict__ A, const float* __restrict__ Bm,
        const float* __restrict__ bias, const float* __restrict__ h0) {
    __shared__ __align__(16) float Xs[2][GBK][GPAD];
    __shared__ __align__(16) float Ws2[2][GBK][GPAD];
    const int tid = threadIdx.x;

    if (blockIdx.x == 0 && blockIdx.y == 0) {   // fold init: runs before lstm
        if (tid == 0) g_bar = 0u;
        for (int i = tid; i < HV; i += 256) g_hh[0][i] = __float2half(h0[i]);
    }

    const int m0 = blockIdx.x * 128, n0 = blockIdx.y * 128;
    const int tx = (tid & 15) << 3, ty = (tid >> 4) << 3;
    const int ln = tid >> 1, lk = (tid & 1) << 3;

    const float* Ald = A + (size_t)(n0 + ln) * DV + lk;
    const float* Bld = Bm + (size_t)(m0 + ln) * DV + lk;
    float4 ax = *(const float4*)(Ald), ay = *(const float4*)(Ald + 4);
    float4 bx = *(const float4*)(Bld), by = *(const float4*)(Bld + 4);

    float acc[8][8];
#pragma unroll
    for (int i = 0; i < 8; ++i)
#pragma unroll
        for (int j = 0; j < 8; ++j) acc[i][j] = 0.f;

    int buf = 0;
#pragma unroll
    for (int m = 0; m < 4; ++m) {
        Xs[0][lk + m][ln] = (&ax.x)[m];   Xs[0][lk + 4 + m][ln] = (&ay.x)[m];
        Ws2[0][lk + m][ln] = (&bx.x)[m];  Ws2[0][lk + 4 + m][ln] = (&by.x)[m];
    }
    __syncthreads();

    const int NKT = DV / GBK;
    for (int kt = 0; kt < NKT; ++kt) {
        if (kt + 1 < NKT) {
            const float* An = Ald + (kt + 1) * GBK;
            const float* Bn = Bld + (kt + 1) * GBK;
            ax = *(const float4*)(An); ay = *(const float4*)(An + 4);
            bx = *(const float4*)(Bn); by = *(const float4*)(Bn + 4);
        }
#pragma unroll
        for (int kk = 0; kk < GBK; ++kk) {
            float av[8], bv[8];
            *(float4*)&av[0] = *(const float4*)&Xs[buf][kk][ty];
            *(float4*)&av[4] = *(const float4*)&Xs[buf][kk][ty + 4];
            *(float4*)&bv[0] = *(const float4*)&Ws2[buf][kk][tx];
            *(float4*)&bv[4] = *(const float4*)&Ws2[buf][kk][tx + 4];
#pragma unroll
            for (int i = 0; i < 8; ++i)
#pragma unroll
                for (int j = 0; j < 8; ++j)
                    acc[i][j] = fmaf(av[i], bv[j], acc[i][j]);
        }
        if (kt + 1 < NKT) {
            buf ^= 1;
            __syncthreads();
#pragma unroll
            for (int m = 0; m < 4; ++m) {
                Xs[buf][lk + m][ln] = (&ax.x)[m];   Xs[buf][lk + 4 + m][ln] = (&ay.x)[m];
                Ws2[buf][lk + m][ln] = (&bx.x)[m];  Ws2[buf][lk + 4 + m][ln] = (&by.x)[m];
            }
            __syncthreads();
        }
    }
    float4 bb0 = *(const float4*)(bias + m0 + tx);
    float4 bb1 = *(const float4*)(bias + m0 + tx + 4);
#pragma unroll
    for (int i = 0; i < 8; ++i) {
        float* cp = g_xp + (size_t)(n0 + ty + i) * R4H + m0 + tx;
        float4 o0, o1;
#pragma unroll
        for (int j = 0; j < 4; ++j) { (&o0.x)[j] = acc[i][j] + (&bb0.x)[j];
                                      (&o1.x)[j] = acc[i][4 + j] + (&bb1.x)[j]; }
        *(float4*)cp = o0; *(float4*)(cp + 4) = o1;
    }
}

// ---------------------------------------------------------------- LSTM (HMMA)
// W tile layout per k-tile (1792 B): [mt0 512B][mt1 512B][mt2 512B][mt3 256B]
// mt<3: submat s (0..3) at s*128, row r at r*16  (a0:r0-7/k0-7 a1:r8-15/k0-7
//       a2:r0-7/k8-15 a3:r8-15/k8-15). mt3: only rows 48-55: k0-7 at +0,
//       k8-15 at +128; ldmatrix lanes for mats 1/3 alias mats 0/2 (discarded).
__global__ void __launch_bounds__(NTH, 1)
lstm_kernel(const float* __restrict__ c0, const float* __restrict__ W_hh,
            const float* __restrict__ b_hh, float* __restrict__ out) {
    extern __shared__ __align__(16) unsigned char smem_raw[];
    __half* Ws = reinterpret_cast<__half*>(smem_raw);
    float* pre_part = reinterpret_cast<float*>(smem_raw + W_BYTES); // [2][64]

    const int tid = threadIdx.x, cta = blockIdx.x;
    const int j0 = cta * JPC;
    int J = HV - j0; if (J > JPC) J = JPC; if (J < 0) J = 0;

    // ---- stage W slice into mma tile layout (once)
    const int TOTH = 128 * 896;
    for (int a = tid; a < TOTH; a += NTH) {
        int kt = a / 896;
        int rem = a - kt * 896;
        int grow, k;
        if (rem < 768) {
            int mt = rem >> 8, u = rem & 255;
            int s = u >> 6, v = u & 63;
            grow = mt * 16 + (s & 1) * 8 + (v >> 3);
            k = kt * 16 + (s >> 1) * 8 + (v & 7);
        } else {
            int u = rem - 768;
            int s2 = u >> 6, v = u & 63;
            grow = 48 + (v >> 3);
            k = kt * 16 + s2 * 8 + (v & 7);
        }
        int jl = grow >> 2, gate = grow & 3;
        float w = (jl < J) ? W_hh[((size_t)gate * HV + (size_t)(j0 + jl)) * HV + k] : 0.f;
        Ws[a] = __float2half(w);
    }

    const int warp = tid >> 5, lane = tid & 31;
    const int mt = warp & 3, khalf = warp >> 2;
    const uint32_t wsm = smem_u32(Ws);
    uint32_t lmaddr;
    if (mt < 3) lmaddr = wsm + mt * 512 + ((lane >> 3) << 7) + ((lane & 7) << 4);
    else        lmaddr = wsm + 1536 + ((lane & 16) << 3) + ((lane & 7) << 4);
    lmaddr += khalf * 64 * 1792;
    const int bbase = khalf * 512;      // uint index into h (64 kts * 8 uints)

    float c_val = 0.f, b_r[4] = {0.f, 0.f, 0.f, 0.f};
    if (tid < J) {
        c_val = c0[j0 + tid];
#pragma unroll
        for (int g = 0; g < 4; ++g) b_r[g] = b_hh[g * HV + j0 + tid];
    }
    float xp_r[4] = {0.f, 0.f, 0.f, 0.f};
    if (tid < J) {
#pragma unroll
        for (int g = 0; g < 4; ++g)
            xp_r[g] = __ldcg(&g_xp[(size_t)g * HV + j0 + tid]);
    }
    __syncthreads();

    volatile unsigned int* barp = &g_bar;
    unsigned bbuf[2][16];
#pragma unroll
    for (int q = 0; q < 16; ++q) { bbuf[0][q] = 0u; bbuf[1][q] = 0u; }

    for (int t = 0; t < STEPS; ++t) {
        const int p = t & 1;
        const unsigned* hp = (const unsigned*)(&g_hh[p][0]);

        float c[4][4];
#pragma unroll
        for (int s = 0; s < 4; ++s)
#pragma unroll
            for (int q = 0; q < 4; ++q) c[s][q] = 0.f;

        // prefetch chunk 0 (8 k-tiles)
        if (lane < 4) {
#pragma unroll
            for (int q = 0; q < 8; ++q) {
                bbuf[0][2 * q]     = __ldcg(hp + bbase + q * 8 + lane);
                bbuf[0][2 * q + 1] = __ldcg(hp + bbase + q * 8 + 4 + lane);
            }
        }
#pragma unroll
        for (int ch = 0; ch < 8; ++ch) {
            const int cur = ch & 1, nxt = cur ^ 1;
            if (ch + 1 < 8 && lane < 4) {
#pragma unroll
                for (int q = 0; q < 8; ++q) {
                    int kk = (ch + 1) * 8 + q;
                    bbuf[nxt][2 * q]     = __ldcg(hp + bbase + kk * 8 + lane);
                    bbuf[nxt][2 * q + 1] = __ldcg(hp + bbase + kk * 8 + 4 + lane);
                }
            }
#pragma unroll
            for (int q = 0; q < 8; ++q) {
                const int kk = ch * 8 + q;
                uint32_t addr = lmaddr + kk * 1792;
                uint32_t a0, a1, a2, a3;
                asm volatile(
                    "ldmatrix.sync.aligned.m8n8.x4.shared.b16 {%0,%1,%2,%3}, [%4];"
                    : "=r"(a0), "=r"(a1), "=r"(a2), "=r"(a3) : "r"(addr));
                float* cc = c[q & 3];
                asm volatile(
                    "mma.sync.aligned.m16n8k16.row.col.f32.f16.f16.f32 "
                    "{%0,%1,%2,%3}, {%4,%5,%6,%7}, {%8,%9}, {%0,%1,%2,%3};"
                    : "+f"(cc[0]), "+f"(cc[1]), "+f"(cc[2]), "+f"(cc[3])
                    : "r"(a0), "r"(a1), "r"(a2), "r"(a3),
                      "r"(bbuf[cur][2 * q]), "r"(bbuf[cur][2 * q + 1]));
            }
        }
        // fold 4 accumulator streams; extract n==0 column
        if ((lane & 3) == 0) {
            float v0 = c[0][0] + c[1][0] + c[2][0] + c[3][0];
            float v2 = c[0][2] + c[1][2] + c[2][2] + c[3][2];
            int row = mt * 16 + (lane >> 2);
            if (row < ROWS)     pre_part[khalf * 64 + row] = v0;
            if (row + 8 < ROWS) pre_part[khalf * 64 + row + 8] = v2;
        }
        __syncthreads();

        if (tid < J) {
            const int rl = tid << 2;
            float pi = xp_r[0] + b_r[0] + pre_part[rl + 0] + pre_part[64 + rl + 0];
            float pf = xp_r[1] + b_r[1] + pre_part[rl + 1] + pre_part[64 + rl + 1];
            float po = xp_r[2] + b_r[2] + pre_part[rl + 2] + pre_part[64 + rl + 2];
            float pg = xp_r[3] + b_r[3] + pre_part[rl + 3] + pre_part[64 + rl + 3];
            float i_t = 1.0f / (1.0f + expf(-pi));
            float f_t = 1.0f / (1.0f + expf(-pf));
            float o_t = 1.0f / (1.0f + expf(-po));
            float g_t = tanhf(pg);
            c_val = c_val * f_t + i_t * g_t;
            float h_n = o_t * tanhf(c_val);
            g_hh[p ^ 1][j0 + tid] = __float2half(h_n);
            size_t oi = (size_t)t * HV + j0 + tid;
            out[oi] = h_n;
            out[OUTSTRIDE + oi] = f_t;
            out[2 * OUTSTRIDE + oi] = i_t;
        }
        // arrive (warp0 program order guarantees h stores precede)
        if (tid == 0) {
            __threadfence();
            atomicAdd(&g_bar, 1u);
        }
        // prefetch next xp while others arrive
        if (t + 1 < STEPS && tid < J) {
#pragma unroll
            for (int g = 0; g < 4; ++g)
                xp_r[g] = __ldcg(&g_xp[(size_t)(t + 1) * R4H + g * HV + j0 + tid]);
        }
        const unsigned tgt = (unsigned)(t + 1) * GRID;
        if (lane == 0) { while (*barp < tgt) {} }
        __syncwarp();
        __threadfence();
    }
}

extern "C" void kernel_launch(void* const* d_in, const int* in_sizes, int n_in,
                              void* d_out, int out_size) {
    const float* input_ = (const float*)d_in[0];
    const float* h0 = (const float*)d_in[1];
    const float* c0 = (const float*)d_in[2];
    const float* W_ih = (const float*)d_in[3];
    const float* b_ih = (const float*)d_in[4];
    const float* W_hh = (const float*)d_in[5];
    const float* b_hh = (const float*)d_in[6];
    float* out = (float*)d_out;

    static int smem_set = 0;
    if (!smem_set) {
        cudaFuncSetAttribute(lstm_kernel, cudaFuncAttributeMaxDynamicSharedMemorySize,
                             LSTM_SMEM);
        smem_set = 1;
    }

    gemm_xp<<<dim3(R4H / 128, STEPS / 128), 256>>>(input_, W_ih, b_ih, h0);
    lstm_kernel<<<GRID, NTH, LSTM_SMEM>>>(c0, W_hh, b_hh, out);
}

// round 5
// speedup vs baseline: 2.9565x; 2.9565x over previous
#include <cuda_runtime.h>
#include <cuda_fp16.h>
#include <cstdint>

#define BV 8
#define TV 512
#define DV 2048
#define HV 2048
#define STEPS (BV * TV)
#define R4H (4 * HV)
#define GRID 148
#define JPC 14
#define ROWS (4 * JPC)
#define NTH 256
#define LSTM_SMEM (ROWS * HV * 2 + 2 * ROWS * 4)
#define OUTSTRIDE ((size_t)STEPS * HV)

typedef unsigned long long u64t;

__device__ float g_xp[(size_t)STEPS * R4H];
__device__ __align__(16) __half g_hh[2][HV];
__device__ unsigned int g_bar;

#define FFMA2(d, a, b) \
    asm volatile("fma.rn.f32x2 %0, %1, %2, %0;" : "+l"(d) : "l"(a), "l"(b))
#define PACK2(d, s) \
    asm volatile("mov.b64 %0, {%1, %1};" : "=l"(d) : "r"(s))
#define UNPACK2(lo, hi, s) \
    asm volatile("mov.b64 {%0, %1}, %2;" : "=r"(lo), "=r"(hi) : "l"(s))

__device__ __forceinline__ __half2 u2h(unsigned u) {
    return *reinterpret_cast<__half2*>(&u);
}

// ---------------------------------------------------------------- GEMM (+init)
#define GBK 16
#define GPAD 132
__global__ void __launch_bounds__(256, 2)
gemm_xp(const float* __restrict__ A, const float* __restrict__ Bm,
        const float* __restrict__ bias, const float* __restrict__ h0) {
    __shared__ __align__(16) float Xs[2][GBK][GPAD];
    __shared__ __align__(16) float Ws2[2][GBK][GPAD];
    const int tid = threadIdx.x;

    if (blockIdx.x == 0 && blockIdx.y == 0) {   // reset shared state each launch
        if (tid == 0) g_bar = 0u;
        for (int i = tid; i < HV; i += 256) g_hh[0][i] = __float2half(h0[i]);
    }

    const int m0 = blockIdx.x * 128, n0 = blockIdx.y * 128;
    const int tx = (tid & 15) << 3, ty = (tid >> 4) << 3;
    const int ln = tid >> 1, lk = (tid & 1) << 3;

    const float* Ald = A + (size_t)(n0 + ln) * DV + lk;
    const float* Bld = Bm + (size_t)(m0 + ln) * DV + lk;
    float4 ax = *(const float4*)(Ald), ay = *(const float4*)(Ald + 4);
    float4 bx = *(const float4*)(Bld), by = *(const float4*)(Bld + 4);

    u64t acc2[8][4];                       // (c[i][2jp], c[i][2jp+1]) packed
    u64t zero2; PACK2(zero2, 0u);
#pragma unroll
    for (int i = 0; i < 8; ++i)
#pragma unroll
        for (int jp = 0; jp < 4; ++jp) acc2[i][jp] = zero2;

    int buf = 0;
#pragma unroll
    for (int m = 0; m < 4; ++m) {
        Xs[0][lk + m][ln] = (&ax.x)[m];   Xs[0][lk + 4 + m][ln] = (&ay.x)[m];
        Ws2[0][lk + m][ln] = (&bx.x)[m];  Ws2[0][lk + 4 + m][ln] = (&by.x)[m];
    }
    __syncthreads();

    const int NKT = DV / GBK;
    for (int kt = 0; kt < NKT; ++kt) {
        if (kt + 1 < NKT) {
            const float* An = Ald + (kt + 1) * GBK;
            const float* Bn = Bld + (kt + 1) * GBK;
            ax = *(const float4*)(An); ay = *(const float4*)(An + 4);
            bx = *(const float4*)(Bn); by = *(const float4*)(Bn + 4);
        }
#pragma unroll
        for (int kk = 0; kk < GBK; ++kk) {
            float av[8];
            *(float4*)&av[0] = *(const float4*)&Xs[buf][kk][ty];
            *(float4*)&av[4] = *(const float4*)&Xs[buf][kk][ty + 4];
            ulonglong2 q0 = *(const ulonglong2*)&Ws2[buf][kk][tx];
            ulonglong2 q1 = *(const ulonglong2*)&Ws2[buf][kk][tx + 4];
            u64t bv2[4] = {q0.x, q0.y, q1.x, q1.y};
#pragma unroll
            for (int i = 0; i < 8; ++i) {
                u64t a2; PACK2(a2, __float_as_uint(av[i]));
#pragma unroll
                for (int jp = 0; jp < 4; ++jp) FFMA2(acc2[i][jp], a2, bv2[jp]);
            }
        }
        if (kt + 1 < NKT) {
            buf ^= 1;
            __syncthreads();
#pragma unroll
            for (int m = 0; m < 4; ++m) {
                Xs[buf][lk + m][ln] = (&ax.x)[m];   Xs[buf][lk + 4 + m][ln] = (&ay.x)[m];
                Ws2[buf][lk + m][ln] = (&bx.x)[m];  Ws2[buf][lk + 4 + m][ln] = (&by.x)[m];
            }
            __syncthreads();
        }
    }
    float4 bb0 = *(const float4*)(bias + m0 + tx);
    float4 bb1 = *(const float4*)(bias + m0 + tx + 4);
    float bvv[8] = {bb0.x, bb0.y, bb0.z, bb0.w, bb1.x, bb1.y, bb1.z, bb1.w};
#pragma unroll
    for (int i = 0; i < 8; ++i) {
        float o[8];
#pragma unroll
        for (int jp = 0; jp < 4; ++jp) {
            unsigned lo, hi;
            UNPACK2(lo, hi, acc2[i][jp]);
            o[2 * jp]     = __uint_as_float(lo) + bvv[2 * jp];
            o[2 * jp + 1] = __uint_as_float(hi) + bvv[2 * jp + 1];
        }
        float* cp = g_xp + (size_t)(n0 + ty + i) * R4H + m0 + tx;
        *(float4*)cp = *(float4*)&o[0];
        *(float4*)(cp + 4) = *(float4*)&o[4];
    }
}

// ---------------------------------------------------------------- LSTM
__global__ void __launch_bounds__(NTH, 1)
lstm_kernel(const float* __restrict__ c0, const float* __restrict__ W_hh,
            const float* __restrict__ b_hh, float* __restrict__ out) {
    extern __shared__ __align__(16) unsigned char smem_raw[];
    __half* Ws = reinterpret_cast<__half*>(smem_raw);
    float* pre_part = reinterpret_cast<float*>(smem_raw + (size_t)ROWS * HV * 2);

    const int tid = threadIdx.x, cta = blockIdx.x;
    const int j0 = cta * JPC;
    int J = HV - j0; if (J > JPC) J = JPC; if (J < 0) J = 0;

    // stage W_hh slice -> SMEM fp16. row rl = jl*4+gate <- W_hh[gate*HV + j0+jl]
    for (int e = tid; e < ROWS * HV; e += NTH) {
        int rl = e >> 11, k = e & (HV - 1);
        int jl = rl >> 2, gate = rl & 3;
        float w = (jl < J) ? W_hh[((size_t)gate * HV + (size_t)(j0 + jl)) * HV + k] : 0.f;
        Ws[e] = __float2half(w);
    }

    const int warp = tid >> 5, lane = tid & 31;
    const int grp = warp >> 1, hf = warp & 1;
    const int kb = hf << 10;
    const int rbase = grp * JPC;

    float c_val = 0.f, b_r[4] = {0.f, 0.f, 0.f, 0.f};
    if (tid < J) {
        c_val = c0[j0 + tid];
#pragma unroll
        for (int g = 0; g < 4; ++g) b_r[g] = b_hh[g * HV + j0 + tid];
    }
    __syncthreads();

    const uint4* Wq = reinterpret_cast<const uint4*>(Ws);
    const size_t wbase = (size_t)rbase * 256 + (size_t)hf * 128 + lane;
    volatile unsigned int* barp = &g_bar;

    float xp_r[4] = {0.f, 0.f, 0.f, 0.f};
    if (tid < J) {
#pragma unroll
        for (int g = 0; g < 4; ++g)
            xp_r[g] = __ldcg(&g_xp[(size_t)g * HV + j0 + tid]);
    }

    const __half2 hz = __float2half2_rn(0.f);

    for (int t = 0; t < STEPS; ++t) {
        const int p = t & 1;

        // ---- h (fp16) -> registers: 4x LDG.128
        uint4 hq[4];
        {
            const uint4* hb4 = (const uint4*)(&g_hh[p][kb + (lane << 3)]);
#pragma unroll
            for (int it = 0; it < 4; ++it) hq[it] = __ldcg(hb4 + it * 32);
        }

        __half2 acc[JPC][4];
#pragma unroll
        for (int r = 0; r < JPC; ++r)
#pragma unroll
            for (int s = 0; s < 4; ++s) acc[r][s] = hz;

#pragma unroll
        for (int it = 0; it < 4; ++it) {
#pragma unroll
            for (int r = 0; r < JPC; ++r) {
                uint4 w = Wq[wbase + (size_t)r * 256 + it * 32];
                acc[r][0] = __hfma2(u2h(w.x), u2h(hq[it].x), acc[r][0]);
                acc[r][1] = __hfma2(u2h(w.y), u2h(hq[it].y), acc[r][1]);
                acc[r][2] = __hfma2(u2h(w.z), u2h(hq[it].z), acc[r][2]);
                acc[r][3] = __hfma2(u2h(w.w), u2h(hq[it].w), acc[r][3]);
            }
        }
#pragma unroll
        for (int r = 0; r < JPC; ++r) {
            float2 f0 = __half22float2(acc[r][0]);
            float2 f1 = __half22float2(acc[r][1]);
            float2 f2 = __half22float2(acc[r][2]);
            float2 f3 = __half22float2(acc[r][3]);
            float v = ((f0.x + f0.y) + (f1.x + f1.y)) +
                      ((f2.x + f2.y) + (f3.x + f3.y));
            v += __shfl_xor_sync(~0u, v, 16);
            v += __shfl_xor_sync(~0u, v, 8);
            v += __shfl_xor_sync(~0u, v, 4);
            v += __shfl_xor_sync(~0u, v, 2);
            v += __shfl_xor_sync(~0u, v, 1);
            if (lane == 0) pre_part[hf * ROWS + rbase + r] = v;
        }
        __syncthreads();

        if (tid < J) {
            const int rl = tid << 2;
            float pi = xp_r[0] + b_r[0] + pre_part[rl + 0] + pre_part[ROWS + rl + 0];
            float pf = xp_r[1] + b_r[1] + pre_part[rl + 1] + pre_part[ROWS + rl + 1];
            float po = xp_r[2] + b_r[2] + pre_part[rl + 2] + pre_part[ROWS + rl + 2];
            float pg = xp_r[3] + b_r[3] + pre_part[rl + 3] + pre_part[ROWS + rl + 3];
            float i_t = __fdividef(1.0f, 1.0f + __expf(-pi));
            float f_t = __fdividef(1.0f, 1.0f + __expf(-pf));
            float o_t = __fdividef(1.0f, 1.0f + __expf(-po));
            float g_t = __fdividef(2.0f, 1.0f + __expf(-2.0f * pg)) - 1.0f;
            c_val = c_val * f_t + i_t * g_t;
            float tc = __fdividef(2.0f, 1.0f + __expf(-2.0f * c_val)) - 1.0f;
            float h_n = o_t * tc;
            g_hh[p ^ 1][j0 + tid] = __float2half(h_n);
            size_t oi = (size_t)t * HV + j0 + tid;
            out[oi] = h_n;
            out[OUTSTRIDE + oi] = f_t;
            out[2 * OUTSTRIDE + oi] = i_t;
        }

        // ---- grid barrier (R3-proven): REDG arrive, volatile-load spin
        __syncthreads();
        if (tid == 0) {
            __threadfence();
            atomicAdd(&g_bar, 1u);
        }
        if (t + 1 < STEPS && tid < J) {
#pragma unroll
            for (int g = 0; g < 4; ++g)
                xp_r[g] = __ldcg(&g_xp[(size_t)(t + 1) * R4H + g * HV + j0 + tid]);
        }
        if (tid == 0) {
            const unsigned tgt = (unsigned)(t + 1) * GRID;
            while (*barp < tgt) {}
            __threadfence();
        }
        __syncthreads();
    }
}

extern "C" void kernel_launch(void* const* d_in, const int* in_sizes, int n_in,
                              void* d_out, int out_size) {
    const float* input_ = (const float*)d_in[0];
    const float* h0 = (const float*)d_in[1];
    const float* c0 = (const float*)d_in[2];
    const float* W_ih = (const float*)d_in[3];
    const float* b_ih = (const float*)d_in[4];
    const float* W_hh = (const float*)d_in[5];
    const float* b_hh = (const float*)d_in[6];
    float* out = (float*)d_out;

    static int smem_set = 0;
    if (!smem_set) {
        cudaFuncSetAttribute(lstm_kernel, cudaFuncAttributeMaxDynamicSharedMemorySize,
                             LSTM_SMEM);
        smem_set = 1;
    }

    gemm_xp<<<dim3(R4H / 128, STEPS / 128), 256>>>(input_, W_ih, b_ih, h0);
    lstm_kernel<<<GRID, NTH, LSTM_SMEM>>>(c0, W_hh, b_hh, out);
}